// round 13
// baseline (speedup 1.0000x reference)
#include <cuda_runtime.h>
#include <cuda_fp16.h>
#include <cooperative_groups.h>

namespace cg = cooperative_groups;

#define NN 100000
#define EE_MAX 1600000
#define DD 128
#define NB_SCAN 98   // ceil(100000/1024)

// -------- scratch (device globals; no allocation allowed) --------
__device__ __half  g_Sh[(size_t)NN * DD];  // GEMM out (prescaled by dinv), fp16
__device__ __half  g_Hh[(size_t)NN * DD];  // layer output, fp16
__device__ float   g_dinv[NN];
__device__ int     g_count[NN];            // zero at entry; k_csr self-cleans
__device__ int     g_rowptr[NN + 1];       // ABSOLUTE after k_csr phase 4
__device__ int     g_cursor[NN];
__device__ int     g_col[EE_MAX];
__device__ int     g_bsum[NB_SCAN];
__device__ int     g_boff[NB_SCAN];
// W in fp16 hi/lo mma-fragment order: per (kt,ntg,lane) uint4 {b0hi2,b1hi2,b0lo2,b1lo2}
__device__ uint4   g_Wf1[8 * 16 * 32];
__device__ uint4   g_Wf2[8 * 16 * 32];

__device__ __forceinline__ unsigned packh2(__half a, __half b) {
    __half2 h = __halves2half2(a, b);
    return *reinterpret_cast<unsigned*>(&h);
}

__device__ __forceinline__ void mma16(float* c, const unsigned* a, const unsigned* b) {
    asm volatile(
        "mma.sync.aligned.m16n8k16.row.col.f32.f16.f16.f32 "
        "{%0,%1,%2,%3}, {%4,%5,%6,%7}, {%8,%9}, {%0,%1,%2,%3};\n"
        : "+f"(c[0]), "+f"(c[1]), "+f"(c[2]), "+f"(c[3])
        : "r"(a[0]), "r"(a[1]), "r"(a[2]), "r"(a[3]), "r"(b[0]), "r"(b[1]));
}

// ============ cooperative CSR kernel: degree -> scan(+dinv) -> boff -> absolutize ============
__global__ void __launch_bounds__(1024)
k_csr(const int* __restrict__ dst, int E) {
    cg::grid_group grid = cg::this_grid();
    int tid = blockIdx.x * 1024 + threadIdx.x;
    int nt = gridDim.x * 1024;

    // phase 1: degree (fire-and-forget REDs, 8 edges per iteration)
    int Ew = E & ~7;
    for (int base = tid * 8; base + 8 <= Ew; base += nt * 8) {
        int4 d0 = *(const int4*)&dst[base];
        int4 d1 = *(const int4*)&dst[base + 4];
        atomicAdd(&g_count[d0.x], 1);
        atomicAdd(&g_count[d0.y], 1);
        atomicAdd(&g_count[d0.z], 1);
        atomicAdd(&g_count[d0.w], 1);
        atomicAdd(&g_count[d1.x], 1);
        atomicAdd(&g_count[d1.y], 1);
        atomicAdd(&g_count[d1.z], 1);
        atomicAdd(&g_count[d1.w], 1);
    }
    if (tid < E - Ew) atomicAdd(&g_count[dst[Ew + tid]], 1);
    grid.sync();

    // phase 2: block-local exclusive scan + dinv + count self-clean
    __shared__ int s[1024];
    int i = tid;
    int v = (i < NN) ? g_count[i] : 0;
    if (i < NN) {
        g_dinv[i] = rsqrtf((float)v + 1.0f);  // +1 self-loop
        g_count[i] = 0;                       // restore invariant for next replay
    }
    s[threadIdx.x] = v;
    __syncthreads();
    #pragma unroll
    for (int off = 1; off < 1024; off <<= 1) {
        int t = (threadIdx.x >= off) ? s[threadIdx.x - off] : 0;
        __syncthreads();
        s[threadIdx.x] += t;
        __syncthreads();
    }
    int local_ex = s[threadIdx.x] - v;
    if (threadIdx.x == 1023) g_bsum[blockIdx.x] = s[1023];
    grid.sync();

    // phase 3: block 0 scans the block sums -> exclusive boff
    if (blockIdx.x == 0) {
        int t = threadIdx.x;
        int bv = (t < NB_SCAN) ? g_bsum[t] : 0;
        if (t < 128) s[t] = bv;
        __syncthreads();
        #pragma unroll
        for (int off = 1; off < 128; off <<= 1) {
            int tv = (t < 128 && t >= off) ? s[t - off] : 0;
            __syncthreads();
            if (t < 128) s[t] += tv;
            __syncthreads();
        }
        if (t < NB_SCAN) g_boff[t] = s[t] - bv;
    }
    grid.sync();

    // phase 4: absolute rowptr + cursor init + terminator
    if (i < NN) {
        int r = local_ex + g_boff[i >> 10];
        g_rowptr[i] = r;
        g_cursor[i] = r;
    } else if (i == NN) {
        g_rowptr[NN] = E;
    }
}

// -------- bucket (normal kernel; cursor pre-initialized to absolute row starts) --------
__global__ void k_bucket(const int* __restrict__ src, const int* __restrict__ dst, int E) {
    int i = blockIdx.x * blockDim.x + threadIdx.x;
    int e = i * 2;
    if (e + 2 <= E) {
        int2 s = *(const int2*)&src[e];
        int2 d = *(const int2*)&dst[e];
        int p0 = atomicAdd(&g_cursor[d.x], 1);
        g_col[p0] = s.x;
        int p1 = atomicAdd(&g_cursor[d.y], 1);
        g_col[p1] = s.y;
    } else {
        for (; e < E; e++) {
            int pos = atomicAdd(&g_cursor[dst[e]], 1);
            g_col[pos] = src[e];
        }
    }
}

// -------- W -> fp16 hi/lo fragment split (m16n8k16 B layout) --------
__global__ void k_wsplit(const float* __restrict__ W, uint4* __restrict__ out) {
    int i = blockIdx.x * blockDim.x + threadIdx.x;
    if (i >= 8 * 16 * 32) return;
    int lane = i & 31;
    int tile = i >> 5;
    int ntg = tile & 15;
    int kt = tile >> 4;
    int tig = lane & 3, g = lane >> 2;
    int k0 = kt * 16, n0 = ntg * 8;
    float w00 = W[(k0 + 2 * tig) * DD + n0 + g];
    float w01 = W[(k0 + 2 * tig + 1) * DD + n0 + g];
    float w10 = W[(k0 + 2 * tig + 8) * DD + n0 + g];
    float w11 = W[(k0 + 2 * tig + 9) * DD + n0 + g];
    __half h00 = __float2half_rn(w00), h01 = __float2half_rn(w01);
    __half h10 = __float2half_rn(w10), h11 = __float2half_rn(w11);
    __half l00 = __float2half_rn(w00 - __half2float(h00));
    __half l01 = __float2half_rn(w01 - __half2float(h01));
    __half l10 = __float2half_rn(w10 - __half2float(h10));
    __half l11 = __float2half_rn(w11 - __half2float(h11));
    uint4 o;
    o.x = packh2(h00, h01);
    o.y = packh2(h10, h11);
    o.z = packh2(l00, l01);
    o.w = packh2(l10, l11);
    out[i] = o;
}

// -------- GEMM1 (standalone, split-fp16, 3 mma, dinv epilogue) --------
#define GSMEM (128 * 132 * 4 + 8 * 16 * 32 * 16)   // 133120

__global__ void __launch_bounds__(1024, 1)
k_gemm1(const float* __restrict__ X, const uint4* __restrict__ Wfrag,
        __half* __restrict__ out, int n) {
    extern __shared__ float sm[];
    float* sX = sm;
    uint4* sW = (uint4*)(sm + 128 * 132);
    int t = threadIdx.x;
    int row0 = blockIdx.x * 128;

    #pragma unroll
    for (int j = t; j < 4096; j += 1024) sW[j] = Wfrag[j];
    #pragma unroll
    for (int j = t; j < 4096; j += 1024) {
        int r = j >> 5, c4 = j & 31;
        int gr = row0 + r;
        float4 v = make_float4(0.f, 0.f, 0.f, 0.f);
        if (gr < n) v = *(const float4*)&X[(size_t)gr * DD + c4 * 4];
        *(float4*)&sX[r * 132 + c4 * 4] = v;
    }
    __syncthreads();

    int lane = t & 31, wid = t >> 5;
    int wr = wid >> 2, wc = wid & 3;
    int g = lane >> 2, tig = lane & 3;

    float c[4][4];
    #pragma unroll
    for (int i2 = 0; i2 < 4; i2++)
        #pragma unroll
        for (int j2 = 0; j2 < 4; j2++) c[i2][j2] = 0.f;

    const float* xb = &sX[(wr * 16 + g) * 132];

    #pragma unroll
    for (int kt = 0; kt < 8; kt++) {
        int k0 = kt * 16;
        float2 p0 = *(const float2*)&xb[k0 + 2 * tig];
        float2 p1 = *(const float2*)&xb[8 * 132 + k0 + 2 * tig];
        float2 p2 = *(const float2*)&xb[k0 + 2 * tig + 8];
        float2 p3 = *(const float2*)&xb[8 * 132 + k0 + 2 * tig + 8];
        __half h00 = __float2half_rn(p0.x), h01 = __float2half_rn(p0.y);
        __half h10 = __float2half_rn(p1.x), h11 = __float2half_rn(p1.y);
        __half h20 = __float2half_rn(p2.x), h21 = __float2half_rn(p2.y);
        __half h30 = __float2half_rn(p3.x), h31 = __float2half_rn(p3.y);
        unsigned ah[4], al[4];
        ah[0] = packh2(h00, h01);
        ah[1] = packh2(h10, h11);
        ah[2] = packh2(h20, h21);
        ah[3] = packh2(h30, h31);
        al[0] = packh2(__float2half_rn(p0.x - __half2float(h00)),
                       __float2half_rn(p0.y - __half2float(h01)));
        al[1] = packh2(__float2half_rn(p1.x - __half2float(h10)),
                       __float2half_rn(p1.y - __half2float(h11)));
        al[2] = packh2(__float2half_rn(p2.x - __half2float(h20)),
                       __float2half_rn(p2.y - __half2float(h21)));
        al[3] = packh2(__float2half_rn(p3.x - __half2float(h30)),
                       __float2half_rn(p3.y - __half2float(h31)));
        #pragma unroll
        for (int nt = 0; nt < 4; nt++) {
            uint4 bf = sW[(kt * 16 + wc * 4 + nt) * 32 + lane];
            unsigned bh[2] = {bf.x, bf.y};
            unsigned bl[2] = {bf.z, bf.w};
            mma16(c[nt], ah, bh);
            mma16(c[nt], al, bh);
            mma16(c[nt], ah, bl);
        }
    }

    int ra = row0 + wr * 16 + g;
    int rb = ra + 8;
    float sa = (ra < n) ? g_dinv[ra] : 1.f;
    float sb = (rb < n) ? g_dinv[rb] : 1.f;
    #pragma unroll
    for (int nt = 0; nt < 4; nt++) {
        int col = wc * 32 + nt * 8 + tig * 2;
        if (ra < n) *(__half2*)&out[(size_t)ra * DD + col] =
            __floats2half2_rn(c[nt][0] * sa, c[nt][1] * sa);
        if (rb < n) *(__half2*)&out[(size_t)rb * DD + col] =
            __floats2half2_rn(c[nt][2] * sb, c[nt][3] * sb);
    }
}

// ============ fused main chain: gather1 -> GEMM2 -> gather2 -> pairs ============
__device__ __forceinline__ void add_h8(float* acc, uint4 u) {
    float2 f0 = __half22float2(*reinterpret_cast<__half2*>(&u.x));
    float2 f1 = __half22float2(*reinterpret_cast<__half2*>(&u.y));
    float2 f2 = __half22float2(*reinterpret_cast<__half2*>(&u.z));
    float2 f3 = __half22float2(*reinterpret_cast<__half2*>(&u.w));
    acc[0] += f0.x; acc[1] += f0.y;
    acc[2] += f1.x; acc[3] += f1.y;
    acc[4] += f2.x; acc[5] += f2.y;
    acc[6] += f3.x; acc[7] += f3.y;
}

template <bool RELU>
__device__ void gather_phase(const float* __restrict__ bias, int hw0, int HW, int lane) {
    float4 b0 = *(const float4*)&bias[lane * 8];
    float4 b1 = *(const float4*)&bias[lane * 8 + 4];
    for (int w = hw0; w < NN; w += HW) {
        int beg = g_rowptr[w];
        int end = g_rowptr[w + 1];
        float dn = g_dinv[w];
        float acc[8] = {0.f, 0.f, 0.f, 0.f, 0.f, 0.f, 0.f, 0.f};
        add_h8(acc, __ldg((const uint4*)&g_Sh[(size_t)w * DD] + lane));  // self-loop
        int j = beg;
        for (; j + 4 <= end; j += 4) {
            int s0 = __ldg(&g_col[j]);
            int s1 = __ldg(&g_col[j + 1]);
            int s2 = __ldg(&g_col[j + 2]);
            int s3 = __ldg(&g_col[j + 3]);
            uint4 u0 = __ldg((const uint4*)&g_Sh[(size_t)s0 * DD] + lane);
            uint4 u1 = __ldg((const uint4*)&g_Sh[(size_t)s1 * DD] + lane);
            uint4 u2 = __ldg((const uint4*)&g_Sh[(size_t)s2 * DD] + lane);
            uint4 u3 = __ldg((const uint4*)&g_Sh[(size_t)s3 * DD] + lane);
            add_h8(acc, u0);
            add_h8(acc, u1);
            add_h8(acc, u2);
            add_h8(acc, u3);
        }
        for (; j < end; j++) {
            int s = __ldg(&g_col[j]);
            add_h8(acc, __ldg((const uint4*)&g_Sh[(size_t)s * DD] + lane));
        }
        float o[8];
        o[0] = fmaf(acc[0], dn, b0.x); o[1] = fmaf(acc[1], dn, b0.y);
        o[2] = fmaf(acc[2], dn, b0.z); o[3] = fmaf(acc[3], dn, b0.w);
        o[4] = fmaf(acc[4], dn, b1.x); o[5] = fmaf(acc[5], dn, b1.y);
        o[6] = fmaf(acc[6], dn, b1.z); o[7] = fmaf(acc[7], dn, b1.w);
        if (RELU) {
            #pragma unroll
            for (int i = 0; i < 8; i++) o[i] = fmaxf(o[i], 0.f);
        }
        uint4 pk;
        *reinterpret_cast<__half2*>(&pk.x) = __floats2half2_rn(o[0], o[1]);
        *reinterpret_cast<__half2*>(&pk.y) = __floats2half2_rn(o[2], o[3]);
        *reinterpret_cast<__half2*>(&pk.z) = __floats2half2_rn(o[4], o[5]);
        *reinterpret_cast<__half2*>(&pk.w) = __floats2half2_rn(o[6], o[7]);
        *((uint4*)&g_Hh[(size_t)w * DD] + lane) = pk;
    }
}

__global__ void __launch_bounds__(1024, 1)
k_main(const float* __restrict__ b1, const float* __restrict__ b2,
       const int* __restrict__ edges, const int* __restrict__ edneg,
       float* __restrict__ out, int P) {
    cg::grid_group grid = cg::this_grid();
    extern __shared__ float sm[];
    int t = threadIdx.x;
    int tidg = blockIdx.x * 1024 + t;
    int HW = gridDim.x * 64;          // total half-warps
    int hw0 = tidg >> 4;
    int lane = t & 15;

    // ---- phase 1: gather layer 1 (relu) : Sh -> Hh ----
    gather_phase<true>(b1, hw0, HW, lane);
    grid.sync();

    // ---- phase 2: GEMM2 (fp16 in, 2 mma, dinv epilogue) : Hh -> Sh ----
    {
        float* sX = sm;
        uint4* sW = (uint4*)(sm + 128 * 132);
        #pragma unroll
        for (int j = t; j < 4096; j += 1024) sW[j] = g_Wf2[j];

        int lane32 = t & 31, wid = t >> 5;
        int wr = wid >> 2, wc = wid & 3;
        int g = lane32 >> 2, tig = lane32 & 3;

        for (int tile = blockIdx.x; tile * 128 < NN; tile += gridDim.x) {
            int row0 = tile * 128;
            __syncthreads();   // protect sX reuse (also fences sW on first iter)
            #pragma unroll
            for (int j = t; j < 4096; j += 1024) {
                int r = j >> 5, c4 = j & 31;
                int gr = row0 + r;
                float4 v = make_float4(0.f, 0.f, 0.f, 0.f);
                if (gr < NN) {
                    uint2 u = *(const uint2*)&g_Hh[(size_t)gr * DD + c4 * 4];
                    float2 f0 = __half22float2(*reinterpret_cast<__half2*>(&u.x));
                    float2 f1 = __half22float2(*reinterpret_cast<__half2*>(&u.y));
                    v = make_float4(f0.x, f0.y, f1.x, f1.y);
                }
                *(float4*)&sX[r * 132 + c4 * 4] = v;
            }
            __syncthreads();

            float c[4][4];
            #pragma unroll
            for (int i2 = 0; i2 < 4; i2++)
                #pragma unroll
                for (int j2 = 0; j2 < 4; j2++) c[i2][j2] = 0.f;

            const float* xb = &sX[(wr * 16 + g) * 132];
            #pragma unroll
            for (int kt = 0; kt < 8; kt++) {
                int k0 = kt * 16;
                float2 p0 = *(const float2*)&xb[k0 + 2 * tig];
                float2 p1 = *(const float2*)&xb[8 * 132 + k0 + 2 * tig];
                float2 p2 = *(const float2*)&xb[k0 + 2 * tig + 8];
                float2 p3 = *(const float2*)&xb[8 * 132 + k0 + 2 * tig + 8];
                unsigned ah[4];
                ah[0] = packh2(__float2half_rn(p0.x), __float2half_rn(p0.y));
                ah[1] = packh2(__float2half_rn(p1.x), __float2half_rn(p1.y));
                ah[2] = packh2(__float2half_rn(p2.x), __float2half_rn(p2.y));
                ah[3] = packh2(__float2half_rn(p3.x), __float2half_rn(p3.y));
                #pragma unroll
                for (int nt = 0; nt < 4; nt++) {
                    uint4 bf = sW[(kt * 16 + wc * 4 + nt) * 32 + lane32];
                    unsigned bh[2] = {bf.x, bf.y};
                    unsigned bl[2] = {bf.z, bf.w};
                    mma16(c[nt], ah, bh);
                    mma16(c[nt], ah, bl);
                }
            }

            int ra = row0 + wr * 16 + g;
            int rb = ra + 8;
            float sa = (ra < NN) ? g_dinv[ra] : 1.f;
            float sb = (rb < NN) ? g_dinv[rb] : 1.f;
            #pragma unroll
            for (int nt = 0; nt < 4; nt++) {
                int col = wc * 32 + nt * 8 + tig * 2;
                if (ra < NN) *(__half2*)&g_Sh[(size_t)ra * DD + col] =
                    __floats2half2_rn(c[nt][0] * sa, c[nt][1] * sa);
                if (rb < NN) *(__half2*)&g_Sh[(size_t)rb * DD + col] =
                    __floats2half2_rn(c[nt][2] * sb, c[nt][3] * sb);
            }
        }
    }
    grid.sync();

    // ---- phase 3: gather layer 2 (no relu) : Sh -> Hh ----
    gather_phase<false>(b2, hw0, HW, lane);
    grid.sync();

    // ---- phase 4: pair dot products ----
    for (int q = hw0; q < 2 * P; q += HW) {
        const int* tab = (q < P) ? edges : edneg;
        int p = (q < P) ? q : q - P;
        int2 ab = __ldg((const int2*)&tab[2 * p]);
        uint4 ua = __ldg((const uint4*)&g_Hh[(size_t)ab.x * DD] + lane);
        uint4 ub = __ldg((const uint4*)&g_Hh[(size_t)ab.y * DD] + lane);
        float2 a0 = __half22float2(*reinterpret_cast<__half2*>(&ua.x));
        float2 a1 = __half22float2(*reinterpret_cast<__half2*>(&ua.y));
        float2 a2 = __half22float2(*reinterpret_cast<__half2*>(&ua.z));
        float2 a3 = __half22float2(*reinterpret_cast<__half2*>(&ua.w));
        float2 c0 = __half22float2(*reinterpret_cast<__half2*>(&ub.x));
        float2 c1 = __half22float2(*reinterpret_cast<__half2*>(&ub.y));
        float2 c2 = __half22float2(*reinterpret_cast<__half2*>(&ub.z));
        float2 c3 = __half22float2(*reinterpret_cast<__half2*>(&ub.w));
        float d = a0.x * c0.x + a0.y * c0.y + a1.x * c1.x + a1.y * c1.y
                + a2.x * c2.x + a2.y * c2.y + a3.x * c3.x + a3.y * c3.y;
        #pragma unroll
        for (int off = 8; off; off >>= 1) d += __shfl_xor_sync(0xffffffffu, d, off);
        if (lane == 0) out[q] = d;
    }
}

extern "C" void kernel_launch(void* const* d_in, const int* in_sizes, int n_in,
                              void* d_out, int out_size) {
    const float* x   = (const float*)d_in[0];
    const float* W1  = (const float*)d_in[1];
    const float* b1  = (const float*)d_in[2];
    const float* W2  = (const float*)d_in[3];
    const float* b2  = (const float*)d_in[4];
    const int* ei    = (const int*)d_in[5];
    const int* edges = (const int*)d_in[6];
    const int* edneg = (const int*)d_in[7];
    float* out = (float*)d_out;

    int E = in_sizes[5] / 2;
    int P = in_sizes[6] / 2;
    const int* src = ei;
    const int* dst = ei + E;

    static cudaStream_t s2 = nullptr;
    static cudaEvent_t evFork = nullptr, evDinv = nullptr, evJoin = nullptr;
    static int gMain = 0;
    if (!s2) {
        cudaStreamCreateWithFlags(&s2, cudaStreamNonBlocking);
        cudaEventCreateWithFlags(&evFork, cudaEventDisableTiming);
        cudaEventCreateWithFlags(&evDinv, cudaEventDisableTiming);
        cudaEventCreateWithFlags(&evJoin, cudaEventDisableTiming);
        cudaFuncSetAttribute((const void*)k_gemm1,
                             cudaFuncAttributeMaxDynamicSharedMemorySize, GSMEM);
        cudaFuncSetAttribute((const void*)k_main,
                             cudaFuncAttributeMaxDynamicSharedMemorySize, GSMEM);
        int dev = 0, sms = 0, maxb = 0;
        cudaGetDevice(&dev);
        cudaDeviceGetAttribute(&sms, cudaDevAttrMultiProcessorCount, dev);
        cudaOccupancyMaxActiveBlocksPerMultiprocessor(&maxb, (const void*)k_main,
                                                      1024, GSMEM);
        gMain = sms * (maxb > 0 ? maxb : 1);
        if (gMain <= 0) gMain = 148;
    }

    void *pSh = nullptr, *pWf1 = nullptr, *pWf2 = nullptr;
    cudaGetSymbolAddress(&pSh, g_Sh);
    cudaGetSymbolAddress(&pWf1, g_Wf1);
    cudaGetSymbolAddress(&pWf2, g_Wf2);

    // ---- fork: CSR build on side stream s2 ----
    cudaEventRecord(evFork, 0);
    cudaStreamWaitEvent(s2, evFork, 0);
    {
        const int* a0 = dst;
        int a1v = E;
        void* args[] = {(void*)&a0, (void*)&a1v};
        cudaLaunchCooperativeKernel((const void*)k_csr, dim3(NB_SCAN), dim3(1024),
                                    args, 0, s2);
    }
    cudaEventRecord(evDinv, s2);                    // dinv + cursor ready
    k_bucket<<<(E / 2 + 256) / 256, 256, 0, s2>>>(src, dst, E);
    cudaEventRecord(evJoin, s2);

    // ---- main stream: W split + GEMM1 (needs only dinv) ----
    int gemm_blocks = (NN + 127) / 128;
    k_wsplit<<<(8 * 16 * 32 + 255) / 256, 256>>>(W1, (uint4*)pWf1);
    k_wsplit<<<(8 * 16 * 32 + 255) / 256, 256>>>(W2, (uint4*)pWf2);
    cudaStreamWaitEvent(0, evDinv, 0);
    k_gemm1<<<gemm_blocks, 1024, GSMEM>>>(x, (const uint4*)pWf1, (__half*)pSh, NN);

    // ---- join, then fused main chain (cooperative) ----
    cudaStreamWaitEvent(0, evJoin, 0);
    {
        const float *a0 = b1, *a1 = b2;
        const int *a2 = edges, *a3 = edneg;
        float* a4 = out;
        int a5 = P;
        void* args[] = {(void*)&a0, (void*)&a1, (void*)&a2,
                        (void*)&a3, (void*)&a4, (void*)&a5};
        cudaLaunchCooperativeKernel((const void*)k_main, dim3(gMain), dim3(1024),
                                    args, GSMEM, 0);
    }
}

// round 14
// speedup vs baseline: 1.3335x; 1.3335x over previous
#include <cuda_runtime.h>
#include <cuda_fp16.h>

#define NN 100000
#define EE_MAX 1600000
#define DD 128
#define NB_SCAN 98   // ceil(100000/1024)

// -------- scratch (device globals; no allocation allowed) --------
__device__ __half  g_Sh[(size_t)NN * DD];  // GEMM out (prescaled by dinv), fp16
__device__ __half  g_Hh[(size_t)NN * DD];  // layer output, fp16
__device__ float   g_dinv[NN];
__device__ int     g_count[NN];
__device__ int     g_rowptr[NN + 1];
__device__ int     g_cursor[NN];
__device__ int     g_col[EE_MAX];
__device__ int     g_bsum[NB_SCAN];
__device__ int     g_boff[NB_SCAN];
__device__ int     g_scanctr;
// W in fp16 hi/lo mma-fragment order: per (kt,ntg,lane) uint4 {b0hi2,b1hi2,b0lo2,b1lo2}
__device__ uint4   g_Wf1[8 * 16 * 32];
__device__ uint4   g_Wf2[8 * 16 * 32];

__device__ __forceinline__ unsigned packh2(__half a, __half b) {
    __half2 h = __halves2half2(a, b);
    return *reinterpret_cast<unsigned*>(&h);
}

__device__ __forceinline__ void mma16(float* c, const unsigned* a, const unsigned* b) {
    asm volatile(
        "mma.sync.aligned.m16n8k16.row.col.f32.f16.f16.f32 "
        "{%0,%1,%2,%3}, {%4,%5,%6,%7}, {%8,%9}, {%0,%1,%2,%3};\n"
        : "+f"(c[0]), "+f"(c[1]), "+f"(c[2]), "+f"(c[3])
        : "r"(a[0]), "r"(a[1]), "r"(a[2]), "r"(a[3]), "r"(b[0]), "r"(b[1]));
}

// -------- CSR build --------
__global__ void k_degree(const int* __restrict__ dst, int E) {
    int i = blockIdx.x * blockDim.x + threadIdx.x;
    if (i == 0) g_scanctr = 0;   // reset last-block counter for fused scan
    int e = i * 8;
    if (e + 8 <= E) {
        int4 d0 = *(const int4*)&dst[e];
        int4 d1 = *(const int4*)&dst[e + 4];
        atomicAdd(&g_count[d0.x], 1);
        atomicAdd(&g_count[d0.y], 1);
        atomicAdd(&g_count[d0.z], 1);
        atomicAdd(&g_count[d0.w], 1);
        atomicAdd(&g_count[d1.x], 1);
        atomicAdd(&g_count[d1.y], 1);
        atomicAdd(&g_count[d1.z], 1);
        atomicAdd(&g_count[d1.w], 1);
    } else {
        for (; e < E; e++) atomicAdd(&g_count[dst[e]], 1);
    }
}

// block-local exclusive scan + dinv; last block scans the block sums (fused scan2)
__global__ void k_scan1(int n) {
    __shared__ int s[1024];
    __shared__ int isLast;
    int i = blockIdx.x * 1024 + threadIdx.x;
    int v = (i < n) ? g_count[i] : 0;
    if (i < n) g_dinv[i] = rsqrtf((float)v + 1.0f);  // +1 self-loop
    s[threadIdx.x] = v;
    __syncthreads();
    #pragma unroll
    for (int off = 1; off < 1024; off <<= 1) {
        int t = (threadIdx.x >= off) ? s[threadIdx.x - off] : 0;
        __syncthreads();
        s[threadIdx.x] += t;
        __syncthreads();
    }
    if (i < n) g_rowptr[i] = s[threadIdx.x] - v;  // exclusive within block
    if (threadIdx.x == 1023) g_bsum[blockIdx.x] = s[1023];
    __threadfence();
    if (threadIdx.x == 0) isLast = (atomicAdd(&g_scanctr, 1) == gridDim.x - 1);
    __syncthreads();
    if (isLast) {
        int t = threadIdx.x;
        int bv = (t < NB_SCAN) ? g_bsum[t] : 0;
        if (t < 128) s[t] = bv;
        __syncthreads();
        #pragma unroll
        for (int off = 1; off < 128; off <<= 1) {
            int tv = (t < 128 && t >= off) ? s[t - off] : 0;
            __syncthreads();
            if (t < 128) s[t] += tv;
            __syncthreads();
        }
        if (t < NB_SCAN) g_boff[t] = s[t] - bv;  // exclusive block offsets
    }
}

__global__ void k_scan3(int n, int E) {
    int i = blockIdx.x * blockDim.x + threadIdx.x;
    if (i < n) {
        int r = g_rowptr[i] + g_boff[i >> 10];
        g_rowptr[i] = r;
        g_cursor[i] = r;
    }
    if (i == 0) g_rowptr[n] = E;
}

__global__ void k_bucket(const int* __restrict__ src, const int* __restrict__ dst, int E) {
    int i = blockIdx.x * blockDim.x + threadIdx.x;
    int e = i * 2;
    if (e + 2 <= E) {
        int2 s = *(const int2*)&src[e];
        int2 d = *(const int2*)&dst[e];
        int p0 = atomicAdd(&g_cursor[d.x], 1);
        g_col[p0] = s.x;
        int p1 = atomicAdd(&g_cursor[d.y], 1);
        g_col[p1] = s.y;
    } else {
        for (; e < E; e++) {
            int pos = atomicAdd(&g_cursor[dst[e]], 1);
            g_col[pos] = src[e];
        }
    }
}

// -------- W -> fp16 hi/lo fragment split (m16n8k16 B layout) --------
__global__ void k_wsplit(const float* __restrict__ W, uint4* __restrict__ out) {
    int i = blockIdx.x * blockDim.x + threadIdx.x;
    if (i >= 8 * 16 * 32) return;
    int lane = i & 31;
    int tile = i >> 5;
    int ntg = tile & 15;
    int kt = tile >> 4;
    int tig = lane & 3, g = lane >> 2;
    int k0 = kt * 16, n0 = ntg * 8;
    float w00 = W[(k0 + 2 * tig) * DD + n0 + g];
    float w01 = W[(k0 + 2 * tig + 1) * DD + n0 + g];
    float w10 = W[(k0 + 2 * tig + 8) * DD + n0 + g];
    float w11 = W[(k0 + 2 * tig + 9) * DD + n0 + g];
    __half h00 = __float2half_rn(w00), h01 = __float2half_rn(w01);
    __half h10 = __float2half_rn(w10), h11 = __float2half_rn(w11);
    __half l00 = __float2half_rn(w00 - __half2float(h00));
    __half l01 = __float2half_rn(w01 - __half2float(h01));
    __half l10 = __float2half_rn(w10 - __half2float(h10));
    __half l11 = __float2half_rn(w11 - __half2float(h11));
    uint4 o;
    o.x = packh2(h00, h01);
    o.y = packh2(h10, h11);
    o.z = packh2(l00, l01);
    o.w = packh2(l10, l11);
    out[i] = o;
}

// -------- GEMM (split-fp16 tensor core), dinv prescale in epilogue --------
// SPLIT_A: fp32 input (layer 1; 3 mma) vs fp16-exact input (layer 2; 2 mma)
#define GSMEM (128 * 132 * 4 + 8 * 16 * 32 * 16)   // 133120

template <typename IN, bool SPLIT_A>
__global__ void __launch_bounds__(1024, 1)
k_gemm(const IN* __restrict__ X, const uint4* __restrict__ Wfrag,
       __half* __restrict__ out, int n) {
    extern __shared__ float sm[];
    float* sX = sm;                         // 128 x 132 (padded) fp32
    uint4* sW = (uint4*)(sm + 128 * 132);   // 8*16*32 fragment uint4s
    int t = threadIdx.x;
    int row0 = blockIdx.x * 128;

    #pragma unroll
    for (int j = t; j < 4096; j += 1024) sW[j] = Wfrag[j];
    #pragma unroll
    for (int j = t; j < 4096; j += 1024) {
        int r = j >> 5, c4 = j & 31;
        int gr = row0 + r;
        float4 v = make_float4(0.f, 0.f, 0.f, 0.f);
        if (gr < n) {
            if constexpr (sizeof(IN) == 4) {
                v = *(const float4*)&X[(size_t)gr * DD + c4 * 4];
            } else {
                uint2 u = *(const uint2*)&X[(size_t)gr * DD + c4 * 4];
                float2 f0 = __half22float2(*reinterpret_cast<__half2*>(&u.x));
                float2 f1 = __half22float2(*reinterpret_cast<__half2*>(&u.y));
                v = make_float4(f0.x, f0.y, f1.x, f1.y);
            }
        }
        *(float4*)&sX[r * 132 + c4 * 4] = v;
    }
    __syncthreads();

    int lane = t & 31, wid = t >> 5;
    int wr = wid >> 2, wc = wid & 3;
    int g = lane >> 2, tig = lane & 3;

    float c[4][4];
    #pragma unroll
    for (int i = 0; i < 4; i++)
        #pragma unroll
        for (int j = 0; j < 4; j++) c[i][j] = 0.f;

    const float* xb = &sX[(wr * 16 + g) * 132];

    #pragma unroll
    for (int kt = 0; kt < 8; kt++) {
        int k0 = kt * 16;
        float2 p0 = *(const float2*)&xb[k0 + 2 * tig];
        float2 p1 = *(const float2*)&xb[8 * 132 + k0 + 2 * tig];
        float2 p2 = *(const float2*)&xb[k0 + 2 * tig + 8];
        float2 p3 = *(const float2*)&xb[8 * 132 + k0 + 2 * tig + 8];
        __half h00 = __float2half_rn(p0.x), h01 = __float2half_rn(p0.y);
        __half h10 = __float2half_rn(p1.x), h11 = __float2half_rn(p1.y);
        __half h20 = __float2half_rn(p2.x), h21 = __float2half_rn(p2.y);
        __half h30 = __float2half_rn(p3.x), h31 = __float2half_rn(p3.y);
        unsigned ah[4], al[4];
        ah[0] = packh2(h00, h01);
        ah[1] = packh2(h10, h11);
        ah[2] = packh2(h20, h21);
        ah[3] = packh2(h30, h31);
        if constexpr (SPLIT_A) {
            al[0] = packh2(__float2half_rn(p0.x - __half2float(h00)),
                           __float2half_rn(p0.y - __half2float(h01)));
            al[1] = packh2(__float2half_rn(p1.x - __half2float(h10)),
                           __float2half_rn(p1.y - __half2float(h11)));
            al[2] = packh2(__float2half_rn(p2.x - __half2float(h20)),
                           __float2half_rn(p2.y - __half2float(h21)));
            al[3] = packh2(__float2half_rn(p3.x - __half2float(h30)),
                           __float2half_rn(p3.y - __half2float(h31)));
        }
        #pragma unroll
        for (int nt = 0; nt < 4; nt++) {
            uint4 bf = sW[(kt * 16 + wc * 4 + nt) * 32 + lane];
            unsigned bh[2] = {bf.x, bf.y};
            unsigned bl[2] = {bf.z, bf.w};
            mma16(c[nt], ah, bh);
            if constexpr (SPLIT_A) mma16(c[nt], al, bh);
            mma16(c[nt], ah, bl);
        }
    }

    int ra = row0 + wr * 16 + g;
    int rb = ra + 8;
    float sa = (ra < n) ? g_dinv[ra] : 1.f;
    float sb = (rb < n) ? g_dinv[rb] : 1.f;
    #pragma unroll
    for (int nt = 0; nt < 4; nt++) {
        int col = wc * 32 + nt * 8 + tig * 2;
        if (ra < n) *(__half2*)&out[(size_t)ra * DD + col] =
            __floats2half2_rn(c[nt][0] * sa, c[nt][1] * sa);
        if (rb < n) *(__half2*)&out[(size_t)rb * DD + col] =
            __floats2half2_rn(c[nt][2] * sb, c[nt][3] * sb);
    }
}

// -------- gather over prescaled rows: H[w] = act( dinv[w]*Σ Sh[s∈N∪{w}] + b ) ----
__device__ __forceinline__ void add_h8(float* acc, uint4 u) {
    float2 f0 = __half22float2(*reinterpret_cast<__half2*>(&u.x));
    float2 f1 = __half22float2(*reinterpret_cast<__half2*>(&u.y));
    float2 f2 = __half22float2(*reinterpret_cast<__half2*>(&u.z));
    float2 f3 = __half22float2(*reinterpret_cast<__half2*>(&u.w));
    acc[0] += f0.x; acc[1] += f0.y;
    acc[2] += f1.x; acc[3] += f1.y;
    acc[4] += f2.x; acc[5] += f2.y;
    acc[6] += f3.x; acc[7] += f3.y;
}

template <bool RELU>
__global__ void k_gather(const float* __restrict__ bias, int n) {
    int w = (blockIdx.x * blockDim.x + threadIdx.x) >> 4;   // node = half-warp
    int lane = threadIdx.x & 15;                            // 16 lanes x 16B = 256B row
    if (w >= n) return;
    int beg = g_rowptr[w];
    int end = g_rowptr[w + 1];
    float dn = g_dinv[w];
    float acc[8] = {0.f, 0.f, 0.f, 0.f, 0.f, 0.f, 0.f, 0.f};
    add_h8(acc, __ldg((const uint4*)&g_Sh[(size_t)w * DD] + lane));  // self-loop
    int j = beg;
    for (; j + 4 <= end; j += 4) {
        int s0 = __ldg(&g_col[j]);
        int s1 = __ldg(&g_col[j + 1]);
        int s2 = __ldg(&g_col[j + 2]);
        int s3 = __ldg(&g_col[j + 3]);
        uint4 u0 = __ldg((const uint4*)&g_Sh[(size_t)s0 * DD] + lane);
        uint4 u1 = __ldg((const uint4*)&g_Sh[(size_t)s1 * DD] + lane);
        uint4 u2 = __ldg((const uint4*)&g_Sh[(size_t)s2 * DD] + lane);
        uint4 u3 = __ldg((const uint4*)&g_Sh[(size_t)s3 * DD] + lane);
        add_h8(acc, u0);
        add_h8(acc, u1);
        add_h8(acc, u2);
        add_h8(acc, u3);
    }
    for (; j < end; j++) {
        int s = __ldg(&g_col[j]);
        add_h8(acc, __ldg((const uint4*)&g_Sh[(size_t)s * DD] + lane));
    }
    float4 b0 = *(const float4*)&bias[lane * 8];
    float4 b1 = *(const float4*)&bias[lane * 8 + 4];
    float o[8];
    o[0] = fmaf(acc[0], dn, b0.x); o[1] = fmaf(acc[1], dn, b0.y);
    o[2] = fmaf(acc[2], dn, b0.z); o[3] = fmaf(acc[3], dn, b0.w);
    o[4] = fmaf(acc[4], dn, b1.x); o[5] = fmaf(acc[5], dn, b1.y);
    o[6] = fmaf(acc[6], dn, b1.z); o[7] = fmaf(acc[7], dn, b1.w);
    if (RELU) {
        #pragma unroll
        for (int i = 0; i < 8; i++) o[i] = fmaxf(o[i], 0.f);
    }
    uint4 pk;
    *reinterpret_cast<__half2*>(&pk.x) = __floats2half2_rn(o[0], o[1]);
    *reinterpret_cast<__half2*>(&pk.y) = __floats2half2_rn(o[2], o[3]);
    *reinterpret_cast<__half2*>(&pk.z) = __floats2half2_rn(o[4], o[5]);
    *reinterpret_cast<__half2*>(&pk.w) = __floats2half2_rn(o[6], o[7]);
    *((uint4*)&g_Hh[(size_t)w * DD] + lane) = pk;
}

// -------- pair dot products: half-warp per pair, uint4 loads --------
__global__ void k_pairs(const int* __restrict__ pos, const int* __restrict__ neg,
                        float* __restrict__ out, int P) {
    int q = (blockIdx.x * blockDim.x + threadIdx.x) >> 4;
    int lane = threadIdx.x & 15;
    if (q >= 2 * P) return;
    const int* tab = (q < P) ? pos : neg;
    int p = (q < P) ? q : q - P;
    int a = __ldg(&tab[2 * p]);
    int b = __ldg(&tab[2 * p + 1]);
    uint4 ua = __ldg((const uint4*)&g_Hh[(size_t)a * DD] + lane);
    uint4 ub = __ldg((const uint4*)&g_Hh[(size_t)b * DD] + lane);
    float2 a0 = __half22float2(*reinterpret_cast<__half2*>(&ua.x));
    float2 a1 = __half22float2(*reinterpret_cast<__half2*>(&ua.y));
    float2 a2 = __half22float2(*reinterpret_cast<__half2*>(&ua.z));
    float2 a3 = __half22float2(*reinterpret_cast<__half2*>(&ua.w));
    float2 c0 = __half22float2(*reinterpret_cast<__half2*>(&ub.x));
    float2 c1 = __half22float2(*reinterpret_cast<__half2*>(&ub.y));
    float2 c2 = __half22float2(*reinterpret_cast<__half2*>(&ub.z));
    float2 c3 = __half22float2(*reinterpret_cast<__half2*>(&ub.w));
    float d = a0.x * c0.x + a0.y * c0.y + a1.x * c1.x + a1.y * c1.y
            + a2.x * c2.x + a2.y * c2.y + a3.x * c3.x + a3.y * c3.y;
    #pragma unroll
    for (int off = 8; off; off >>= 1) d += __shfl_xor_sync(0xffffffffu, d, off);
    if (lane == 0) out[q] = d;
}

extern "C" void kernel_launch(void* const* d_in, const int* in_sizes, int n_in,
                              void* d_out, int out_size) {
    const float* x   = (const float*)d_in[0];
    const float* W1  = (const float*)d_in[1];
    const float* b1  = (const float*)d_in[2];
    const float* W2  = (const float*)d_in[3];
    const float* b2  = (const float*)d_in[4];
    const int* ei    = (const int*)d_in[5];
    const int* edges = (const int*)d_in[6];
    const int* edneg = (const int*)d_in[7];
    float* out = (float*)d_out;

    int E = in_sizes[5] / 2;
    int P = in_sizes[6] / 2;
    const int* src = ei;
    const int* dst = ei + E;

    static cudaStream_t s2 = nullptr;
    static cudaEvent_t evFork = nullptr, evDinv = nullptr, evJoin = nullptr;
    if (!s2) {
        cudaStreamCreateWithFlags(&s2, cudaStreamNonBlocking);
        cudaEventCreateWithFlags(&evFork, cudaEventDisableTiming);
        cudaEventCreateWithFlags(&evDinv, cudaEventDisableTiming);
        cudaEventCreateWithFlags(&evJoin, cudaEventDisableTiming);
        cudaFuncSetAttribute((const void*)k_gemm<float, true>,
                             cudaFuncAttributeMaxDynamicSharedMemorySize, GSMEM);
        cudaFuncSetAttribute((const void*)k_gemm<__half, false>,
                             cudaFuncAttributeMaxDynamicSharedMemorySize, GSMEM);
    }

    void *pSh = nullptr, *pHh = nullptr, *pWf1 = nullptr, *pWf2 = nullptr, *pCnt = nullptr;
    cudaGetSymbolAddress(&pSh, g_Sh);
    cudaGetSymbolAddress(&pHh, g_Hh);
    cudaGetSymbolAddress(&pWf1, g_Wf1);
    cudaGetSymbolAddress(&pWf2, g_Wf2);
    cudaGetSymbolAddress(&pCnt, g_count);

    // ---- fork: CSR build on side stream s2 ----
    cudaEventRecord(evFork, 0);
    cudaStreamWaitEvent(s2, evFork, 0);
    cudaMemsetAsync(pCnt, 0, NN * sizeof(int), s2);
    k_degree<<<(E / 8 + 256) / 256, 256, 0, s2>>>(dst, E);
    k_scan1<<<NB_SCAN, 1024, 0, s2>>>(NN);          // + dinv + fused scan2
    cudaEventRecord(evDinv, s2);                    // dinv ready for GEMM1 epilogue
    k_scan3<<<(NN + 255) / 256, 256, 0, s2>>>(NN, E);
    k_bucket<<<(E / 2 + 256) / 256, 256, 0, s2>>>(src, dst, E);
    cudaEventRecord(evJoin, s2);

    // ---- main stream: W split + GEMM1 (needs only dinv from side chain) ----
    int gemm_blocks = (NN + 127) / 128;
    k_wsplit<<<(8 * 16 * 32 + 255) / 256, 256>>>(W1, (uint4*)pWf1);
    k_wsplit<<<(8 * 16 * 32 + 255) / 256, 256>>>(W2, (uint4*)pWf2);
    cudaStreamWaitEvent(0, evDinv, 0);
    k_gemm<float, true><<<gemm_blocks, 1024, GSMEM>>>(x, (const uint4*)pWf1,
                                                      (__half*)pSh, NN);

    // ---- join (CSR complete), then dependent chain ----
    cudaStreamWaitEvent(0, evJoin, 0);

    int gather_blocks = (NN * 16 + 255) / 256;
    k_gather<true><<<gather_blocks, 256>>>(b1, NN);
    k_gemm<__half, false><<<gemm_blocks, 1024, GSMEM>>>((const __half*)pHh,
                                                        (const uint4*)pWf2,
                                                        (__half*)pSh, NN);
    k_gather<false><<<gather_blocks, 256>>>(b2, NN);
    int pair_blocks = (2 * P * 16 + 255) / 256;
    k_pairs<<<pair_blocks, 256>>>(edges, edneg, out, P);
}